// round 4
// baseline (speedup 1.0000x reference)
#include <cuda_runtime.h>
#include <cuda_bf16.h>

#define NN 50000
#define EE 800000
#define DIN 128
#define DHID 128
#define DOUT 64

// ---------------- device scratch (static, no runtime allocation) ----------------
__device__ int   g_is64;           // 1 if edge_index is int64, 0 if int32
__device__ int   g_deg[NN];        // per-dst degree
__device__ int   g_cur[NN];        // fill cursors
__device__ int   g_off[NN + 1];    // CSR offsets (by dst)
__device__ int   g_src[EE];        // src node id per CSR slot
__device__ float g_y[(size_t)NN * 256]; // layer1 GEMM out: [:,0:128]=x@W1_l, [:,128:256]=x@W1_r
__device__ float g_h[(size_t)NN * 128]; // layer1 activations
__device__ float g_z[(size_t)NN * 128]; // layer2 GEMM out: [:,0:64]=h@W2_l, [:,64:128]=h@W2_r

// ---------------- dtype detection ----------------
// Sample first 256 values as int64. Real int64 indices lie in [0, NN).
// int32 data reinterpreted as int64 fuses two values -> huge numbers.
// Only touches p64[0..255]: in-bounds for both dtypes (int32 buffer spans p64[0..EE)).
__global__ void detect_kernel(const void* ei) {
    if (threadIdx.x == 0 && blockIdx.x == 0) {
        const long long* p64 = (const long long*)ei;
        int ok = 1;
        for (int i = 0; i < 256; i++) {
            long long v = p64[i];
            if (v < 0 || v >= NN) { ok = 0; break; }
        }
        g_is64 = ok;
    }
}

// ---------------- CSR build ----------------
__global__ void zero_counts() {
    int i = blockIdx.x * blockDim.x + threadIdx.x;
    if (i < NN) { g_deg[i] = 0; g_cur[i] = 0; }
}

__global__ void hist_kernel(const void* eiv) {
    int e = blockIdx.x * blockDim.x + threadIdx.x;
    if (e < EE) {
        long long d = g_is64 ? ((const long long*)eiv)[EE + e]
                             : (long long)((const int*)eiv)[EE + e];
        if ((unsigned long long)d < NN)
            atomicAdd(&g_deg[(int)d], 1);
    }
}

// single-block exclusive scan of g_deg -> g_off (50000 elements)
__global__ void scan_kernel() {
    __shared__ int warpsum[32];
    int t = threadIdx.x;           // 1024 threads
    int lane = t & 31, wid = t >> 5;
    int carry = 0;
    for (int base = 0; base < NN; base += 1024) {
        int v = (base + t < NN) ? g_deg[base + t] : 0;
        int s = v;
        #pragma unroll
        for (int d = 1; d < 32; d <<= 1) {
            int n = __shfl_up_sync(0xffffffffu, s, d);
            if (lane >= d) s += n;
        }
        if (lane == 31) warpsum[wid] = s;
        __syncthreads();
        if (t < 32) {
            int w = warpsum[t];
            int t2 = w;
            #pragma unroll
            for (int d = 1; d < 32; d <<= 1) {
                int n = __shfl_up_sync(0xffffffffu, t2, d);
                if (lane >= d) t2 += n;
            }
            warpsum[t] = t2;  // inclusive warp totals
        }
        __syncthreads();
        int warpoff = (wid > 0) ? warpsum[wid - 1] : 0;
        int incl = warpoff + s;
        if (base + t < NN) g_off[base + t] = carry + incl - v;
        int total = warpsum[31];
        __syncthreads();   // protect warpsum before next iteration
        carry += total;
    }
    if (t == 0) g_off[NN] = carry;  // == EE
}

__global__ void fill_kernel(const void* eiv) {
    int e = blockIdx.x * blockDim.x + threadIdx.x;
    if (e < EE) {
        long long s, d;
        if (g_is64) {
            s = ((const long long*)eiv)[e];
            d = ((const long long*)eiv)[EE + e];
        } else {
            s = ((const int*)eiv)[e];
            d = ((const int*)eiv)[EE + e];
        }
        if ((unsigned long long)s < NN && (unsigned long long)d < NN) {
            int pos = g_off[(int)d] + atomicAdd(&g_cur[(int)d], 1);
            if ((unsigned)pos < EE) g_src[pos] = (int)s;
        }
    }
}

// ---------------- dual-weight GEMM: Y[r, 0:OC]=X@Wl, Y[r, OC:2OC]=X@Wr ----------------
// K fixed = 128. Block computes 64 rows x 64 cols; threads 256 (16x16), 4x4 micro-tile.
template <int OC>
__global__ void __launch_bounds__(256) gemm_dual(
    const float* __restrict__ X, const float* __restrict__ Wl,
    const float* __restrict__ Wr, float* __restrict__ Y, int nrows)
{
    const int OCT = 2 * OC;
    __shared__ float xs[64][68];   // [row][k], row stride 68 (272B, 16B aligned)
    __shared__ float ws[64][64];   // [k][col]

    int r0 = blockIdx.x * 64;
    int cb = blockIdx.y * 64;
    const float* W = (cb < OC) ? Wl : Wr;
    int wc0 = (cb < OC) ? cb : (cb - OC);

    int t = threadIdx.x;
    int tx = t & 15, ty = t >> 4;

    float acc[4][4] = {};

    for (int k0 = 0; k0 < 128; k0 += 64) {
        #pragma unroll
        for (int i = 0; i < 4; i++) {
            int r = (t >> 4) + i * 16;
            int kq = (t & 15) * 4;
            float4 xv = make_float4(0.f, 0.f, 0.f, 0.f);
            if (r0 + r < nrows)
                xv = *(const float4*)(X + (size_t)(r0 + r) * 128 + k0 + kq);
            *(float4*)&xs[r][kq] = xv;
        }
        #pragma unroll
        for (int i = 0; i < 4; i++) {
            int k = (t >> 4) + i * 16;
            int c = (t & 15) * 4;
            float4 wv = *(const float4*)(W + (size_t)(k0 + k) * OC + wc0 + c);
            *(float4*)&ws[k][c] = wv;
        }
        __syncthreads();

        #pragma unroll 16
        for (int k = 0; k < 64; k++) {
            float a0 = xs[ty * 4 + 0][k];
            float a1 = xs[ty * 4 + 1][k];
            float a2 = xs[ty * 4 + 2][k];
            float a3 = xs[ty * 4 + 3][k];
            float4 b = *(float4*)&ws[k][tx * 4];
            acc[0][0] += a0 * b.x; acc[0][1] += a0 * b.y; acc[0][2] += a0 * b.z; acc[0][3] += a0 * b.w;
            acc[1][0] += a1 * b.x; acc[1][1] += a1 * b.y; acc[1][2] += a1 * b.z; acc[1][3] += a1 * b.w;
            acc[2][0] += a2 * b.x; acc[2][1] += a2 * b.y; acc[2][2] += a2 * b.z; acc[2][3] += a2 * b.w;
            acc[3][0] += a3 * b.x; acc[3][1] += a3 * b.y; acc[3][2] += a3 * b.z; acc[3][3] += a3 * b.w;
        }
        __syncthreads();
    }

    #pragma unroll
    for (int i = 0; i < 4; i++) {
        int r = r0 + ty * 4 + i;
        if (r < nrows) {
            float4 o = make_float4(acc[i][0], acc[i][1], acc[i][2], acc[i][3]);
            *(float4*)(Y + (size_t)r * OCT + cb + tx * 4) = o;
        }
    }
}

// ---------------- aggregation (pull, no atomics) ----------------
// layer 1: h[n,t] = relu( mean_src(yl[src,t]) + b1[t] + yr[n,t] ),  y stride 256
__global__ void agg1_kernel(const float* __restrict__ b1) {
    int n = blockIdx.x;
    int t = threadIdx.x;  // 128
    int beg = g_off[n], end = g_off[n + 1];
    float s = 0.f;
    int k = beg;
    for (; k + 3 < end; k += 4) {
        int s0 = g_src[k], s1 = g_src[k + 1], s2 = g_src[k + 2], s3 = g_src[k + 3];
        s += g_y[(size_t)s0 * 256 + t] + g_y[(size_t)s1 * 256 + t]
           + g_y[(size_t)s2 * 256 + t] + g_y[(size_t)s3 * 256 + t];
    }
    for (; k < end; k++) s += g_y[(size_t)g_src[k] * 256 + t];
    int deg = end - beg;
    float c = (deg > 0) ? (float)deg : 1.0f;
    float v = s / c + b1[t] + g_y[(size_t)n * 256 + 128 + t];
    g_h[(size_t)n * 128 + t] = fmaxf(v, 0.f);
}

// layer 2: out[n,t] = mean_src(zl[src,t]) + b2[t] + zr[n,t],  z stride 128
__global__ void agg2_kernel(const float* __restrict__ b2, float* __restrict__ out) {
    int n = blockIdx.x;
    int t = threadIdx.x;  // 64
    int beg = g_off[n], end = g_off[n + 1];
    float s = 0.f;
    int k = beg;
    for (; k + 3 < end; k += 4) {
        int s0 = g_src[k], s1 = g_src[k + 1], s2 = g_src[k + 2], s3 = g_src[k + 3];
        s += g_z[(size_t)s0 * 128 + t] + g_z[(size_t)s1 * 128 + t]
           + g_z[(size_t)s2 * 128 + t] + g_z[(size_t)s3 * 128 + t];
    }
    for (; k < end; k++) s += g_z[(size_t)g_src[k] * 128 + t];
    int deg = end - beg;
    float c = (deg > 0) ? (float)deg : 1.0f;
    out[(size_t)n * 64 + t] = s / c + b2[t] + g_z[(size_t)n * 128 + 64 + t];
}

// ---------------- launch ----------------
extern "C" void kernel_launch(void* const* d_in, const int* in_sizes, int n_in,
                              void* d_out, int out_size) {
    // Identify inputs by element count (robust to harness input ordering).
    //   x: 6,400,000  edge_index: 1,600,000 (int32 OR int64 -> runtime-detected)
    //   W1_l / W1_r: 16,384 (l first)  b1: 128
    //   W2_l / W2_r:  8,192 (l first)  b2: 64
    const float *x = 0, *W1l = 0, *b1 = 0, *W1r = 0, *W2l = 0, *b2 = 0, *W2r = 0;
    const void* ei = 0;
    for (int i = 0; i < n_in; i++) {
        int s = in_sizes[i];
        if (s == NN * DIN)            x = (const float*)d_in[i];
        else if (s == 2 * EE)         ei = d_in[i];
        else if (s == DIN * DHID)   { if (!W1l) W1l = (const float*)d_in[i]; else W1r = (const float*)d_in[i]; }
        else if (s == DHID * DOUT)  { if (!W2l) W2l = (const float*)d_in[i]; else W2r = (const float*)d_in[i]; }
        else if (s == DHID)           b1 = (const float*)d_in[i];
        else if (s == DOUT)           b2 = (const float*)d_in[i];
    }
    float* out = (float*)d_out;

    float *yp, *hp, *zp;
    cudaGetSymbolAddress((void**)&yp, g_y);
    cudaGetSymbolAddress((void**)&hp, g_h);
    cudaGetSymbolAddress((void**)&zp, g_z);

    // CSR build
    detect_kernel<<<1, 32>>>(ei);
    zero_counts<<<(NN + 255) / 256, 256>>>();
    hist_kernel<<<(EE + 255) / 256, 256>>>(ei);
    scan_kernel<<<1, 1024>>>();
    fill_kernel<<<(EE + 255) / 256, 256>>>(ei);

    // layer 1: transform then aggregate
    {
        dim3 grid((NN + 63) / 64, 4);   // 256 output cols in 64-wide tiles
        gemm_dual<128><<<grid, 256>>>(x, W1l, W1r, yp, NN);
    }
    agg1_kernel<<<NN, 128>>>(b1);

    // layer 2
    {
        dim3 grid((NN + 63) / 64, 2);   // 128 output cols in 64-wide tiles
        gemm_dual<64><<<grid, 256>>>(hp, W2l, W2r, zp, NN);
    }
    agg2_kernel<<<NN, 64>>>(b2, out);
}

// round 6
// speedup vs baseline: 2.1586x; 2.1586x over previous
#include <cuda_runtime.h>
#include <cuda_bf16.h>
#include <mma.h>
#include <cstdint>

using namespace nvcuda;

#define NN 50000
#define EE 800000
#define DIN 128
#define DHID 128
#define DOUT 64
#define NBLK 196   // ceil(NN/256)

// ---------------- device scratch ----------------
__device__ int   g_is64;
__device__ int   g_deg[NN];
__device__ int   g_cur[NN];
__device__ int   g_off[NN + 1];
__device__ int   g_bsum[NBLK];
__device__ int   g_boff[NBLK];
__device__ int   g_src[EE];
__device__ __align__(16) float g_y[(size_t)NN * 256]; // [:,0:128]=x@W1l, [:,128:256]=x@W1r
__device__ __align__(16) float g_h[(size_t)NN * 128];
__device__ __align__(16) float g_z[(size_t)NN * 128]; // [:,0:64]=h@W2l, [:,64:128]=h@W2r
// split-bf16 weights, [K][OCT] row-major
__device__ __align__(16) __nv_bfloat16 g_w1hi[128 * 256];
__device__ __align__(16) __nv_bfloat16 g_w1lo[128 * 256];
__device__ __align__(16) __nv_bfloat16 g_w2hi[128 * 128];
__device__ __align__(16) __nv_bfloat16 g_w2lo[128 * 128];

// ---------------- dtype detect ----------------
__global__ void detect_kernel(const void* ei) {
    if (threadIdx.x == 0 && blockIdx.x == 0) {
        const long long* p = (const long long*)ei;
        int ok = 1;
        for (int i = 0; i < 256; i++) { long long v = p[i]; if (v < 0 || v >= NN) { ok = 0; break; } }
        g_is64 = ok;
    }
}

// ---------------- CSR build ----------------
__global__ void zero_counts() {
    int i = blockIdx.x * blockDim.x + threadIdx.x;
    if (i < NN) { g_deg[i] = 0; g_cur[i] = 0; }
}
__global__ void hist_kernel(const void* eiv) {
    int e = blockIdx.x * blockDim.x + threadIdx.x;
    if (e < EE) {
        long long d = g_is64 ? ((const long long*)eiv)[EE + e] : (long long)((const int*)eiv)[EE + e];
        if ((unsigned long long)d < NN) atomicAdd(&g_deg[(int)d], 1);
    }
}
__global__ void scan1() {
    __shared__ int ws[8], woff[8];
    int b = blockIdx.x, t = threadIdx.x, i = b * 256 + t;
    int v = (i < NN) ? g_deg[i] : 0;
    int lane = t & 31, w = t >> 5;
    int s = v;
    #pragma unroll
    for (int d = 1; d < 32; d <<= 1) { int n = __shfl_up_sync(0xffffffffu, s, d); if (lane >= d) s += n; }
    if (lane == 31) ws[w] = s;
    __syncthreads();
    if (t == 0) { int acc = 0; for (int j = 0; j < 8; j++) { woff[j] = acc; acc += ws[j]; } g_bsum[b] = acc; }
    __syncthreads();
    if (i < NN) g_off[i] = woff[w] + s - v;
}
__global__ void scan2() {
    __shared__ int ws[8], woff[8];
    int t = threadIdx.x;
    int v = (t < NBLK) ? g_bsum[t] : 0;
    int lane = t & 31, w = t >> 5;
    int s = v;
    #pragma unroll
    for (int d = 1; d < 32; d <<= 1) { int n = __shfl_up_sync(0xffffffffu, s, d); if (lane >= d) s += n; }
    if (lane == 31) ws[w] = s;
    __syncthreads();
    if (t == 0) { int acc = 0; for (int j = 0; j < 8; j++) { woff[j] = acc; acc += ws[j]; } g_off[NN] = acc; }
    __syncthreads();
    if (t < NBLK) g_boff[t] = woff[w] + s - v;
}
__global__ void scan3() {
    int i = blockIdx.x * blockDim.x + threadIdx.x;
    if (i < NN) g_off[i] += g_boff[i >> 8];
}
__global__ void fill_kernel(const void* eiv) {
    int e = blockIdx.x * blockDim.x + threadIdx.x;
    if (e < EE) {
        long long s, d;
        if (g_is64) { s = ((const long long*)eiv)[e]; d = ((const long long*)eiv)[EE + e]; }
        else        { s = ((const int*)eiv)[e];       d = ((const int*)eiv)[EE + e]; }
        if ((unsigned long long)s < NN && (unsigned long long)d < NN) {
            int pos = g_off[(int)d] + atomicAdd(&g_cur[(int)d], 1);
            if ((unsigned)pos < EE) g_src[pos] = (int)s;
        }
    }
}

// ---------------- weight prep: split bf16, [K][OCT] row-major ----------------
__global__ void prep_w(const float* __restrict__ W1l, const float* __restrict__ W1r,
                       const float* __restrict__ W2l, const float* __restrict__ W2r) {
    int idx = blockIdx.x * blockDim.x + threadIdx.x;
    if (idx >= 128 * 256 + 128 * 128) return;
    float w;
    __nv_bfloat16 *dh, *dl;
    if (idx < 128 * 256) {
        int k = idx >> 8, c = idx & 255;
        w = (c < 128) ? W1l[k * 128 + c] : W1r[k * 128 + (c - 128)];
        dh = g_w1hi + idx; dl = g_w1lo + idx;
    } else {
        int e = idx - 128 * 256;
        int k = e >> 7, c = e & 127;
        w = (c < 64) ? W2l[k * 64 + c] : W2r[k * 64 + (c - 64)];
        dh = g_w2hi + e; dl = g_w2lo + e;
    }
    __nv_bfloat16 hi = __float2bfloat16(w);
    __nv_bfloat16 lo = __float2bfloat16(w - __bfloat162float(hi));
    *dh = hi; *dl = lo;
}

// ---------------- WMMA bf16 split GEMM ----------------
// Y[64-row tile, 64-col chunk] = X @ W  (K=128), split-bf16: hi*hi + hi*lo + lo*hi
// Block 256 thr (8 warps: 2 row-halves x 4 col-quarters); each warp 32x16.
// Dynamic smem: xhi[64][136], xlo[64][136], whi[128][72], wlo[128][72] (bf16) = 71680 B.
template <int OCT>
__global__ void __launch_bounds__(256) gemm_wmma(const float* __restrict__ X,
                                                 const __nv_bfloat16* __restrict__ Whi,
                                                 const __nv_bfloat16* __restrict__ Wlo,
                                                 float* __restrict__ Y, int nrows) {
    extern __shared__ unsigned char sm[];
    __nv_bfloat16* xhi = (__nv_bfloat16*)sm;            // 64*136
    __nv_bfloat16* xlo = xhi + 64 * 136;
    __nv_bfloat16* whs = xlo + 64 * 136;                // 128*72
    __nv_bfloat16* wls = whs + 128 * 72;

    int r0 = blockIdx.x * 64;
    int c0 = blockIdx.y * 64;
    int tid = threadIdx.x;

    // load + split X tile (64 rows x 128 k)
    for (int i = tid; i < 64 * 32; i += 256) {
        int r = i >> 5, q = i & 31;
        float4 v = make_float4(0.f, 0.f, 0.f, 0.f);
        if (r0 + r < nrows) v = ((const float4*)X)[(size_t)(r0 + r) * 32 + q];
        __nv_bfloat16 h0 = __float2bfloat16(v.x), h1 = __float2bfloat16(v.y);
        __nv_bfloat16 h2 = __float2bfloat16(v.z), h3 = __float2bfloat16(v.w);
        __nv_bfloat16 l0 = __float2bfloat16(v.x - __bfloat162float(h0));
        __nv_bfloat16 l1 = __float2bfloat16(v.y - __bfloat162float(h1));
        __nv_bfloat16 l2 = __float2bfloat16(v.z - __bfloat162float(h2));
        __nv_bfloat16 l3 = __float2bfloat16(v.w - __bfloat162float(h3));
        int base = r * 136 + q * 4;
        xhi[base] = h0; xhi[base + 1] = h1; xhi[base + 2] = h2; xhi[base + 3] = h3;
        xlo[base] = l0; xlo[base + 1] = l1; xlo[base + 2] = l2; xlo[base + 3] = l3;
    }
    // load W chunk (128 k x 64 cols), uint2 = 4 bf16
    for (int i = tid; i < 128 * 16; i += 256) {
        int k = i >> 4, q = i & 15;
        *(uint2*)&whs[k * 72 + q * 4] = *(const uint2*)(Whi + (size_t)k * OCT + c0 + q * 4);
        *(uint2*)&wls[k * 72 + q * 4] = *(const uint2*)(Wlo + (size_t)k * OCT + c0 + q * 4);
    }
    __syncthreads();

    int wid = tid >> 5;
    int wr = (wid & 1) * 32;        // warp row offset (2 halves of 32)
    int wc = (wid >> 1) * 16;       // warp col offset (4 quarters of 16)

    wmma::fragment<wmma::accumulator, 16, 16, 16, float> acc0, acc1;
    wmma::fill_fragment(acc0, 0.f);
    wmma::fill_fragment(acc1, 0.f);

    #pragma unroll
    for (int k = 0; k < 8; k++) {
        wmma::fragment<wmma::matrix_a, 16, 16, 16, __nv_bfloat16, wmma::row_major> ah0, ah1, al0, al1;
        wmma::fragment<wmma::matrix_b, 16, 16, 16, __nv_bfloat16, wmma::row_major> bh, bl;
        wmma::load_matrix_sync(ah0, xhi + (size_t)wr * 136 + k * 16, 136);
        wmma::load_matrix_sync(ah1, xhi + (size_t)(wr + 16) * 136 + k * 16, 136);
        wmma::load_matrix_sync(al0, xlo + (size_t)wr * 136 + k * 16, 136);
        wmma::load_matrix_sync(al1, xlo + (size_t)(wr + 16) * 136 + k * 16, 136);
        wmma::load_matrix_sync(bh, whs + (size_t)(k * 16) * 72 + wc, 72);
        wmma::load_matrix_sync(bl, wls + (size_t)(k * 16) * 72 + wc, 72);
        wmma::mma_sync(acc0, ah0, bh, acc0);
        wmma::mma_sync(acc0, ah0, bl, acc0);
        wmma::mma_sync(acc0, al0, bh, acc0);
        wmma::mma_sync(acc1, ah1, bh, acc1);
        wmma::mma_sync(acc1, ah1, bl, acc1);
        wmma::mma_sync(acc1, al1, bh, acc1);
    }
    __syncthreads();   // everyone done reading smem; reuse as f32 buffer

    float* fbuf = (float*)sm;       // 64 x 72 floats = 18432 B
    wmma::store_matrix_sync(fbuf + (size_t)wr * 72 + wc, acc0, 72, wmma::mem_row_major);
    wmma::store_matrix_sync(fbuf + (size_t)(wr + 16) * 72 + wc, acc1, 72, wmma::mem_row_major);
    __syncthreads();

    // guarded copy to global
    for (int i = tid; i < 64 * 16; i += 256) {
        int r = i >> 4, q = i & 15;
        if (r0 + r < nrows)
            ((float4*)(Y + (size_t)(r0 + r) * OCT + c0))[q] = ((const float4*)(fbuf + (size_t)r * 72))[q];
    }
}

// ---------------- aggregation (pull, warp-per-node, vectorized) ----------------
__global__ void agg1_kernel(const float* __restrict__ b1) {
    int n = blockIdx.x, t = threadIdx.x;  // 32 threads, float4 per lane (128 cols)
    const float4* Y4 = (const float4*)g_y;    // row stride 64 float4
    int beg = g_off[n], end = g_off[n + 1];
    float4 a = make_float4(0.f, 0.f, 0.f, 0.f);
    int k = beg;
    for (; k + 3 < end; k += 4) {
        int s0 = g_src[k], s1 = g_src[k + 1], s2 = g_src[k + 2], s3 = g_src[k + 3];
        float4 v0 = Y4[(size_t)s0 * 64 + t], v1 = Y4[(size_t)s1 * 64 + t];
        float4 v2 = Y4[(size_t)s2 * 64 + t], v3 = Y4[(size_t)s3 * 64 + t];
        a.x += v0.x + v1.x + v2.x + v3.x;
        a.y += v0.y + v1.y + v2.y + v3.y;
        a.z += v0.z + v1.z + v2.z + v3.z;
        a.w += v0.w + v1.w + v2.w + v3.w;
    }
    for (; k < end; k++) {
        float4 v = Y4[(size_t)g_src[k] * 64 + t];
        a.x += v.x; a.y += v.y; a.z += v.z; a.w += v.w;
    }
    int deg = end - beg;
    float inv = 1.0f / ((deg > 0) ? (float)deg : 1.0f);
    float4 self = Y4[(size_t)n * 64 + 32 + t];
    float4 bb = ((const float4*)b1)[t];
    float4 r;
    r.x = fmaxf(a.x * inv + bb.x + self.x, 0.f);
    r.y = fmaxf(a.y * inv + bb.y + self.y, 0.f);
    r.z = fmaxf(a.z * inv + bb.z + self.z, 0.f);
    r.w = fmaxf(a.w * inv + bb.w + self.w, 0.f);
    ((float4*)g_h)[(size_t)n * 32 + t] = r;
}

__global__ void agg2_kernel(const float* __restrict__ b2, float* __restrict__ out) {
    int n = blockIdx.x, t = threadIdx.x;  // 32 threads, float2 per lane (64 cols)
    const float2* Z2 = (const float2*)g_z;    // row stride 64 float2
    int beg = g_off[n], end = g_off[n + 1];
    float2 a = make_float2(0.f, 0.f);
    int k = beg;
    for (; k + 3 < end; k += 4) {
        int s0 = g_src[k], s1 = g_src[k + 1], s2 = g_src[k + 2], s3 = g_src[k + 3];
        float2 v0 = Z2[(size_t)s0 * 64 + t], v1 = Z2[(size_t)s1 * 64 + t];
        float2 v2 = Z2[(size_t)s2 * 64 + t], v3 = Z2[(size_t)s3 * 64 + t];
        a.x += v0.x + v1.x + v2.x + v3.x;
        a.y += v0.y + v1.y + v2.y + v3.y;
    }
    for (; k < end; k++) {
        float2 v = Z2[(size_t)g_src[k] * 64 + t];
        a.x += v.x; a.y += v.y;
    }
    int deg = end - beg;
    float inv = 1.0f / ((deg > 0) ? (float)deg : 1.0f);
    float2 self = Z2[(size_t)n * 64 + 32 + t];
    float2 bb = ((const float2*)b2)[t];
    float2 r;
    r.x = a.x * inv + bb.x + self.x;
    r.y = a.y * inv + bb.y + self.y;
    ((float2*)out)[(size_t)n * 32 + t] = r;
}

// ---------------- launch ----------------
extern "C" void kernel_launch(void* const* d_in, const int* in_sizes, int n_in,
                              void* d_out, int out_size) {
    const float *x = 0, *W1l = 0, *b1 = 0, *W1r = 0, *W2l = 0, *b2 = 0, *W2r = 0;
    const void* ei = 0;
    for (int i = 0; i < n_in; i++) {
        int s = in_sizes[i];
        if (s == NN * DIN)            x = (const float*)d_in[i];
        else if (s == 2 * EE)         ei = d_in[i];
        else if (s == DIN * DHID)   { if (!W1l) W1l = (const float*)d_in[i]; else W1r = (const float*)d_in[i]; }
        else if (s == DHID * DOUT)  { if (!W2l) W2l = (const float*)d_in[i]; else W2r = (const float*)d_in[i]; }
        else if (s == DHID)           b1 = (const float*)d_in[i];
        else if (s == DOUT)           b2 = (const float*)d_in[i];
    }
    float* out = (float*)d_out;

    float *yp, *hp, *zp;
    __nv_bfloat16 *w1h, *w1l_, *w2h, *w2l_;
    cudaGetSymbolAddress((void**)&yp, g_y);
    cudaGetSymbolAddress((void**)&hp, g_h);
    cudaGetSymbolAddress((void**)&zp, g_z);
    cudaGetSymbolAddress((void**)&w1h, g_w1hi);
    cudaGetSymbolAddress((void**)&w1l_, g_w1lo);
    cudaGetSymbolAddress((void**)&w2h, g_w2hi);
    cudaGetSymbolAddress((void**)&w2l_, g_w2lo);

    const int SMEM = (2 * 64 * 136 + 2 * 128 * 72) * 2;  // 71680
    cudaFuncSetAttribute(gemm_wmma<256>, cudaFuncAttributeMaxDynamicSharedMemorySize, SMEM);
    cudaFuncSetAttribute(gemm_wmma<128>, cudaFuncAttributeMaxDynamicSharedMemorySize, SMEM);

    // CSR build
    detect_kernel<<<1, 32>>>(ei);
    zero_counts<<<NBLK, 256>>>();
    hist_kernel<<<(EE + 255) / 256, 256>>>(ei);
    scan1<<<NBLK, 256>>>();
    scan2<<<1, 256>>>();
    scan3<<<NBLK, 256>>>();
    fill_kernel<<<(EE + 255) / 256, 256>>>(ei);

    // split-bf16 weights
    prep_w<<<(128 * 256 + 128 * 128 + 255) / 256, 256>>>(W1l, W1r, W2l, W2r);

    // layer 1
    {
        dim3 grid((NN + 63) / 64, 4);
        gemm_wmma<256><<<grid, 256, SMEM>>>(x, w1h, w1l_, yp, NN);
    }
    agg1_kernel<<<NN, 32>>>(b1);

    // layer 2
    {
        dim3 grid((NN + 63) / 64, 2);
        gemm_wmma<128><<<grid, 256, SMEM>>>(hp, w2h, w2l_, zp, NN);
    }
    agg2_kernel<<<NN, 32>>>(b2, out);
}

// round 9
// speedup vs baseline: 2.2713x; 1.0522x over previous
#include <cuda_runtime.h>
#include <cuda_bf16.h>
#include <mma.h>
#include <cstdint>

using namespace nvcuda;

#define NN 50000
#define NR 50048   // padded rows (multiple of 64) for unguarded tile stores
#define EE 800000
#define DIN 128
#define DHID 128
#define DOUT 64
#define NBLK 196   // ceil(NN/256)

// ---------------- device scratch ----------------
__device__ int   g_is64;
__device__ int   g_deg[NN];
__device__ int   g_cur[NN];
__device__ int   g_off[NN + 1];
__device__ int   g_bsum[NBLK];
__device__ int   g_boff[NBLK];
__device__ int   g_src[EE];
__device__ __align__(16) float g_y[(size_t)NR * 256]; // [:,0:128]=x@W1l, [:,128:256]=x@W1r
__device__ __align__(16) float g_h[(size_t)NR * 128];
__device__ __align__(16) float g_z[(size_t)NR * 128]; // [:,0:64]=h@W2l, [:,64:128]=h@W2r
// split-bf16 weights, [K][OCT] row-major
__device__ __align__(16) __nv_bfloat16 g_w1hi[128 * 256];
__device__ __align__(16) __nv_bfloat16 g_w1lo[128 * 256];
__device__ __align__(16) __nv_bfloat16 g_w2hi[128 * 128];
__device__ __align__(16) __nv_bfloat16 g_w2lo[128 * 128];

// ---------------- dtype detect ----------------
__global__ void detect_kernel(const void* ei) {
    if (threadIdx.x == 0 && blockIdx.x == 0) {
        const long long* p = (const long long*)ei;
        int ok = 1;
        for (int i = 0; i < 256; i++) { long long v = p[i]; if (v < 0 || v >= NN) { ok = 0; break; } }
        g_is64 = ok;
    }
}

// ---------------- CSR build ----------------
__global__ void zero_counts() {
    int i = blockIdx.x * blockDim.x + threadIdx.x;
    if (i < NN) { g_deg[i] = 0; g_cur[i] = 0; }
}
__global__ void hist_kernel(const void* eiv) {
    int e = blockIdx.x * blockDim.x + threadIdx.x;
    if (e < EE) {
        long long d = g_is64 ? ((const long long*)eiv)[EE + e] : (long long)((const int*)eiv)[EE + e];
        if ((unsigned long long)d < NN) atomicAdd(&g_deg[(int)d], 1);
    }
}
__global__ void scan1() {
    __shared__ int ws[8], woff[8];
    int b = blockIdx.x, t = threadIdx.x, i = b * 256 + t;
    int v = (i < NN) ? g_deg[i] : 0;
    int lane = t & 31, w = t >> 5;
    int s = v;
    #pragma unroll
    for (int d = 1; d < 32; d <<= 1) { int n = __shfl_up_sync(0xffffffffu, s, d); if (lane >= d) s += n; }
    if (lane == 31) ws[w] = s;
    __syncthreads();
    if (t == 0) { int acc = 0; for (int j = 0; j < 8; j++) { woff[j] = acc; acc += ws[j]; } g_bsum[b] = acc; }
    __syncthreads();
    if (i < NN) g_off[i] = woff[w] + s - v;
}
__global__ void scan2() {
    __shared__ int ws[8], woff[8];
    int t = threadIdx.x;
    int v = (t < NBLK) ? g_bsum[t] : 0;
    int lane = t & 31, w = t >> 5;
    int s = v;
    #pragma unroll
    for (int d = 1; d < 32; d <<= 1) { int n = __shfl_up_sync(0xffffffffu, s, d); if (lane >= d) s += n; }
    if (lane == 31) ws[w] = s;
    __syncthreads();
    if (t == 0) { int acc = 0; for (int j = 0; j < 8; j++) { woff[j] = acc; acc += ws[j]; } g_off[NN] = acc; }
    __syncthreads();
    if (t < NBLK) g_boff[t] = woff[w] + s - v;
}
__global__ void scan3() {
    int i = blockIdx.x * blockDim.x + threadIdx.x;
    if (i < NN) g_off[i] += g_boff[i >> 8];
}
__global__ void fill_kernel(const void* eiv) {
    int e = blockIdx.x * blockDim.x + threadIdx.x;
    if (e < EE) {
        long long s, d;
        if (g_is64) { s = ((const long long*)eiv)[e]; d = ((const long long*)eiv)[EE + e]; }
        else        { s = ((const int*)eiv)[e];       d = ((const int*)eiv)[EE + e]; }
        if ((unsigned long long)s < NN && (unsigned long long)d < NN) {
            int pos = g_off[(int)d] + atomicAdd(&g_cur[(int)d], 1);
            if ((unsigned)pos < EE) g_src[pos] = (int)s;
        }
    }
}

// ---------------- weight prep: split bf16, [K][OCT] row-major ----------------
__global__ void prep_w(const float* __restrict__ W1l, const float* __restrict__ W1r,
                       const float* __restrict__ W2l, const float* __restrict__ W2r) {
    int idx = blockIdx.x * blockDim.x + threadIdx.x;
    if (idx >= 128 * 256 + 128 * 128) return;
    float w;
    __nv_bfloat16 *dh, *dl;
    if (idx < 128 * 256) {
        int k = idx >> 8, c = idx & 255;
        w = (c < 128) ? W1l[k * 128 + c] : W1r[k * 128 + (c - 128)];
        dh = g_w1hi + idx; dl = g_w1lo + idx;
    } else {
        int e = idx - 128 * 256;
        int k = e >> 7, c = e & 127;
        w = (c < 64) ? W2l[k * 64 + c] : W2r[k * 64 + (c - 64)];
        dh = g_w2hi + e; dl = g_w2lo + e;
    }
    __nv_bfloat16 hi = __float2bfloat16(w);
    __nv_bfloat16 lo = __float2bfloat16(w - __bfloat162float(hi));
    *dh = hi; *dl = lo;
}

// ---------------- WMMA bf16 split GEMM (v2) ----------------
// Block: 64 rows, loops over 128-col chunks of OCT. X split ONCE per block.
// 8 warps = 2 row-groups x 4 col-groups; warp tile 32x32 (2x2 accum frags).
// Split-bf16: Y = Ahi*Bhi + Ahi*Blo + Alo*Bhi (12 MMA per 8 frag loads per k-step).
// Smem: xhi/xlo [64][136] + whi/wlo [128][136] bf16 = 104448 B.
template <int OCT>
__global__ void __launch_bounds__(256) gemm_wmma(const float* __restrict__ X,
                                                 const __nv_bfloat16* __restrict__ Whi,
                                                 const __nv_bfloat16* __restrict__ Wlo,
                                                 float* __restrict__ Y, int nrows) {
    extern __shared__ unsigned char sm[];
    __nv_bfloat16* xhi = (__nv_bfloat16*)sm;            // 64*136
    __nv_bfloat16* xlo = xhi + 64 * 136;
    __nv_bfloat16* whs = xlo + 64 * 136;                // 128*136
    __nv_bfloat16* wls = whs + 128 * 136;

    int r0 = blockIdx.x * 64;
    int tid = threadIdx.x;

    // load + split X tile (64 rows x 128 k) ONCE
    for (int i = tid; i < 64 * 32; i += 256) {
        int r = i >> 5, q = i & 31;
        float4 v = make_float4(0.f, 0.f, 0.f, 0.f);
        if (r0 + r < nrows) v = ((const float4*)X)[(size_t)(r0 + r) * 32 + q];
        __nv_bfloat16 h0 = __float2bfloat16(v.x), h1 = __float2bfloat16(v.y);
        __nv_bfloat16 h2 = __float2bfloat16(v.z), h3 = __float2bfloat16(v.w);
        __nv_bfloat16 l0 = __float2bfloat16(v.x - __bfloat162float(h0));
        __nv_bfloat16 l1 = __float2bfloat16(v.y - __bfloat162float(h1));
        __nv_bfloat16 l2 = __float2bfloat16(v.z - __bfloat162float(h2));
        __nv_bfloat16 l3 = __float2bfloat16(v.w - __bfloat162float(h3));
        int base = r * 136 + q * 4;
        xhi[base] = h0; xhi[base + 1] = h1; xhi[base + 2] = h2; xhi[base + 3] = h3;
        xlo[base] = l0; xlo[base + 1] = l1; xlo[base + 2] = l2; xlo[base + 3] = l3;
    }

    int wid = tid >> 5;
    int wr = (wid & 1) * 32;        // warp row offset
    int wc = (wid >> 1) * 32;       // warp col offset within 128-col chunk

    #pragma unroll
    for (int c0 = 0; c0 < OCT; c0 += 128) {
        __syncthreads();   // X ready (iter 0) / prior-iter reads of W smem done
        // load W chunk: 128 k x 128 cols, hi+lo (uint2 = 4 bf16)
        for (int i = tid; i < 128 * 32; i += 256) {
            int k = i >> 5, q = i & 31;
            *(uint2*)&whs[k * 136 + q * 4] = *(const uint2*)(Whi + (size_t)k * OCT + c0 + q * 4);
            *(uint2*)&wls[k * 136 + q * 4] = *(const uint2*)(Wlo + (size_t)k * OCT + c0 + q * 4);
        }
        __syncthreads();

        wmma::fragment<wmma::accumulator, 16, 16, 16, float> acc[2][2];
        wmma::fill_fragment(acc[0][0], 0.f);
        wmma::fill_fragment(acc[0][1], 0.f);
        wmma::fill_fragment(acc[1][0], 0.f);
        wmma::fill_fragment(acc[1][1], 0.f);

        #pragma unroll
        for (int k = 0; k < 8; k++) {
            wmma::fragment<wmma::matrix_a, 16, 16, 16, __nv_bfloat16, wmma::row_major> ah[2], al[2];
            wmma::fragment<wmma::matrix_b, 16, 16, 16, __nv_bfloat16, wmma::row_major> bh[2], bl[2];
            wmma::load_matrix_sync(ah[0], xhi + (size_t)wr * 136 + k * 16, 136);
            wmma::load_matrix_sync(ah[1], xhi + (size_t)(wr + 16) * 136 + k * 16, 136);
            wmma::load_matrix_sync(al[0], xlo + (size_t)wr * 136 + k * 16, 136);
            wmma::load_matrix_sync(al[1], xlo + (size_t)(wr + 16) * 136 + k * 16, 136);
            wmma::load_matrix_sync(bh[0], whs + (size_t)(k * 16) * 136 + wc, 136);
            wmma::load_matrix_sync(bh[1], whs + (size_t)(k * 16) * 136 + wc + 16, 136);
            wmma::load_matrix_sync(bl[0], wls + (size_t)(k * 16) * 136 + wc, 136);
            wmma::load_matrix_sync(bl[1], wls + (size_t)(k * 16) * 136 + wc + 16, 136);
            #pragma unroll
            for (int i = 0; i < 2; i++)
                #pragma unroll
                for (int j = 0; j < 2; j++) {
                    wmma::mma_sync(acc[i][j], ah[i], bh[j], acc[i][j]);
                    wmma::mma_sync(acc[i][j], ah[i], bl[j], acc[i][j]);
                    wmma::mma_sync(acc[i][j], al[i], bh[j], acc[i][j]);
                }
        }

        // store direct to global (Y padded to NR rows -> unguarded OK)
        #pragma unroll
        for (int i = 0; i < 2; i++)
            #pragma unroll
            for (int j = 0; j < 2; j++)
                wmma::store_matrix_sync(Y + (size_t)(r0 + wr + i * 16) * OCT + c0 + wc + j * 16,
                                        acc[i][j], OCT, wmma::mem_row_major);
    }
}

// ---------------- aggregation (pull, warp-per-node, vectorized) ----------------
__global__ void agg1_kernel(const float* __restrict__ b1) {
    int n = blockIdx.x, t = threadIdx.x;  // 32 threads, float4 per lane (128 cols)
    const float4* Y4 = (const float4*)g_y;    // row stride 64 float4
    int beg = g_off[n], end = g_off[n + 1];
    float4 a = make_float4(0.f, 0.f, 0.f, 0.f);
    int k = beg;
    for (; k + 3 < end; k += 4) {
        int s0 = g_src[k], s1 = g_src[k + 1], s2 = g_src[k + 2], s3 = g_src[k + 3];
        float4 v0 = Y4[(size_t)s0 * 64 + t], v1 = Y4[(size_t)s1 * 64 + t];
        float4 v2 = Y4[(size_t)s2 * 64 + t], v3 = Y4[(size_t)s3 * 64 + t];
        a.x += v0.x + v1.x + v2.x + v3.x;
        a.y += v0.y + v1.y + v2.y + v3.y;
        a.z += v0.z + v1.z + v2.z + v3.z;
        a.w += v0.w + v1.w + v2.w + v3.w;
    }
    for (; k < end; k++) {
        float4 v = Y4[(size_t)g_src[k] * 64 + t];
        a.x += v.x; a.y += v.y; a.z += v.z; a.w += v.w;
    }
    int deg = end - beg;
    float inv = 1.0f / ((deg > 0) ? (float)deg : 1.0f);
    float4 self = Y4[(size_t)n * 64 + 32 + t];
    float4 bb = ((const float4*)b1)[t];
    float4 r;
    r.x = fmaxf(a.x * inv + bb.x + self.x, 0.f);
    r.y = fmaxf(a.y * inv + bb.y + self.y, 0.f);
    r.z = fmaxf(a.z * inv + bb.z + self.z, 0.f);
    r.w = fmaxf(a.w * inv + bb.w + self.w, 0.f);
    ((float4*)g_h)[(size_t)n * 32 + t] = r;
}

__global__ void agg2_kernel(const float* __restrict__ b2, float* __restrict__ out) {
    int n = blockIdx.x, t = threadIdx.x;  // 32 threads, float2 per lane (64 cols)
    const float2* Z2 = (const float2*)g_z;    // row stride 64 float2
    int beg = g_off[n], end = g_off[n + 1];
    float2 a = make_float2(0.f, 0.f);
    int k = beg;
    for (; k + 3 < end; k += 4) {
        int s0 = g_src[k], s1 = g_src[k + 1], s2 = g_src[k + 2], s3 = g_src[k + 3];
        float2 v0 = Z2[(size_t)s0 * 64 + t], v1 = Z2[(size_t)s1 * 64 + t];
        float2 v2 = Z2[(size_t)s2 * 64 + t], v3 = Z2[(size_t)s3 * 64 + t];
        a.x += v0.x + v1.x + v2.x + v3.x;
        a.y += v0.y + v1.y + v2.y + v3.y;
    }
    for (; k < end; k++) {
        float2 v = Z2[(size_t)g_src[k] * 64 + t];
        a.x += v.x; a.y += v.y;
    }
    int deg = end - beg;
    float inv = 1.0f / ((deg > 0) ? (float)deg : 1.0f);
    float2 self = Z2[(size_t)n * 64 + 32 + t];
    float2 bb = ((const float2*)b2)[t];
    float2 r;
    r.x = a.x * inv + bb.x + self.x;
    r.y = a.y * inv + bb.y + self.y;
    ((float2*)out)[(size_t)n * 32 + t] = r;
}

// ---------------- launch ----------------
extern "C" void kernel_launch(void* const* d_in, const int* in_sizes, int n_in,
                              void* d_out, int out_size) {
    const float *x = 0, *W1l = 0, *b1 = 0, *W1r = 0, *W2l = 0, *b2 = 0, *W2r = 0;
    const void* ei = 0;
    for (int i = 0; i < n_in; i++) {
        int s = in_sizes[i];
        if (s == NN * DIN)            x = (const float*)d_in[i];
        else if (s == 2 * EE)         ei = d_in[i];
        else if (s == DIN * DHID)   { if (!W1l) W1l = (const float*)d_in[i]; else W1r = (const float*)d_in[i]; }
        else if (s == DHID * DOUT)  { if (!W2l) W2l = (const float*)d_in[i]; else W2r = (const float*)d_in[i]; }
        else if (s == DHID)           b1 = (const float*)d_in[i];
        else if (s == DOUT)           b2 = (const float*)d_in[i];
    }
    float* out = (float*)d_out;

    float *yp, *hp, *zp;
    __nv_bfloat16 *w1h, *w1l_, *w2h, *w2l_;
    cudaGetSymbolAddress((void**)&yp, g_y);
    cudaGetSymbolAddress((void**)&hp, g_h);
    cudaGetSymbolAddress((void**)&zp, g_z);
    cudaGetSymbolAddress((void**)&w1h, g_w1hi);
    cudaGetSymbolAddress((void**)&w1l_, g_w1lo);
    cudaGetSymbolAddress((void**)&w2h, g_w2hi);
    cudaGetSymbolAddress((void**)&w2l_, g_w2lo);

    const int SMEM = (2 * 64 * 136 + 2 * 128 * 136) * 2;  // 104448
    cudaFuncSetAttribute(gemm_wmma<256>, cudaFuncAttributeMaxDynamicSharedMemorySize, SMEM);
    cudaFuncSetAttribute(gemm_wmma<128>, cudaFuncAttributeMaxDynamicSharedMemorySize, SMEM);

    // Order chosen so launch #4 (ncu's profiled slot) = gemm1.
    prep_w<<<(128 * 256 + 128 * 128 + 255) / 256, 256>>>(W1l, W1r, W2l, W2r);
    detect_kernel<<<1, 32>>>(ei);
    zero_counts<<<NBLK, 256>>>();

    // layer 1 GEMM (independent of CSR)
    gemm_wmma<256><<<(NN + 63) / 64, 256, SMEM>>>(x, w1h, w1l_, yp, NN);

    // CSR build
    hist_kernel<<<(EE + 255) / 256, 256>>>(ei);
    scan1<<<NBLK, 256>>>();
    scan2<<<1, 256>>>();
    scan3<<<NBLK, 256>>>();
    fill_kernel<<<(EE + 255) / 256, 256>>>(ei);

    agg1_kernel<<<NN, 32>>>(b1);
    gemm_wmma<128><<<(NN + 63) / 64, 256, SMEM>>>(hp, w2h, w2l_, zp, NN);
    agg2_kernel<<<NN, 32>>>(b2, out);
}